// round 1
// baseline (speedup 1.0000x reference)
#include <cuda_runtime.h>

#define D 128
#define MAXN 50000

// Scratch: support = (1-alpha)*hi + alpha*h0 accumulated in place.
__device__ float g_support[MAXN * D];

// support[i] = alpha * h0[i]
__global__ void init_support_kernel(const float* __restrict__ h0,
                                    const float* __restrict__ alpha_p, int n4) {
    int i = blockIdx.x * blockDim.x + threadIdx.x;
    if (i >= n4) return;
    float a = *alpha_p;
    float4 h = reinterpret_cast<const float4*>(h0)[i];
    float4 o = make_float4(a * h.x, a * h.y, a * h.z, a * h.w);
    reinterpret_cast<float4*>(g_support)[i] = o;
}

// One warp per edge: support[row[e]] += (1-alpha) * vals[e] * input[col[e]]
// Each lane handles one float4 (4 of 128 features), vectorized red.global.
__global__ void edge_kernel(const float* __restrict__ input,
                            const float* __restrict__ vals,
                            const int* __restrict__ row,
                            const int* __restrict__ col,
                            const float* __restrict__ alpha_p, int E) {
    int t = blockIdx.x * blockDim.x + threadIdx.x;
    int e = t >> 5;
    int lane = t & 31;
    if (e >= E) return;
    int r = row[e];
    int c = col[e];
    float v = vals[e] * (1.0f - *alpha_p);
    float4 x = reinterpret_cast<const float4*>(input + (size_t)c * D)[lane];
    float* dst = g_support + (size_t)r * D + lane * 4;
    asm volatile("red.global.add.v4.f32 [%0], {%1,%2,%3,%4};"
                 :: "l"(dst), "f"(v * x.x), "f"(v * x.y), "f"(v * x.z), "f"(v * x.w)
                 : "memory");
}

// out = theta * (support @ W) + (1-theta) * support
// Warp per row; lane j owns output cols 4j..4j+3. W rows streamed via L1 (__ldg),
// support row staged in shared for scalar broadcast.
__global__ void gemm_kernel(const float* __restrict__ W,
                            const float* __restrict__ lamda_p,
                            const int* __restrict__ l_p,
                            float* __restrict__ out, int N) {
    __shared__ float sSup[8][D];
    int wib = threadIdx.x >> 5;
    int lane = threadIdx.x & 31;
    int rowi = blockIdx.x * 8 + wib;
    if (rowi >= N) return;

    float theta = logf(*lamda_p / (float)(*l_p) + 1.0f);
    float om = 1.0f - theta;

    const float* sup = g_support + (size_t)rowi * D;
    float4 s4 = reinterpret_cast<const float4*>(sup)[lane];
    reinterpret_cast<float4*>(sSup[wib])[lane] = s4;
    __syncwarp();

    float acc0 = 0.f, acc1 = 0.f, acc2 = 0.f, acc3 = 0.f;
#pragma unroll 8
    for (int k = 0; k < D; k++) {
        float s = sSup[wib][k];  // broadcast LDS
        float4 w4 = __ldg(reinterpret_cast<const float4*>(W + (size_t)k * D) + lane);
        acc0 = fmaf(s, w4.x, acc0);
        acc1 = fmaf(s, w4.y, acc1);
        acc2 = fmaf(s, w4.z, acc2);
        acc3 = fmaf(s, w4.w, acc3);
    }

    float4 o = make_float4(theta * acc0 + om * s4.x,
                           theta * acc1 + om * s4.y,
                           theta * acc2 + om * s4.z,
                           theta * acc3 + om * s4.w);
    reinterpret_cast<float4*>(out + (size_t)rowi * D)[lane] = o;
}

extern "C" void kernel_launch(void* const* d_in, const int* in_sizes, int n_in,
                              void* d_out, int out_size) {
    const float* input  = (const float*)d_in[0];
    const float* h0     = (const float*)d_in[1];
    const float* vals   = (const float*)d_in[2];
    const float* W      = (const float*)d_in[3];
    const float* lamda  = (const float*)d_in[4];
    const float* alpha  = (const float*)d_in[5];
    const int*   row    = (const int*)d_in[6];
    const int*   col    = (const int*)d_in[7];
    const int*   l      = (const int*)d_in[8];
    float* out = (float*)d_out;

    int N = in_sizes[0] / D;
    int E = in_sizes[2];

    int n4 = N * D / 4;
    init_support_kernel<<<(n4 + 255) / 256, 256>>>(h0, alpha, n4);

    long long totalThreads = (long long)E * 32;
    int eBlocks = (int)((totalThreads + 255) / 256);
    edge_kernel<<<eBlocks, 256>>>(input, vals, row, col, alpha, E);

    gemm_kernel<<<(N + 7) / 8, 256>>>(W, lamda, l, out, N);
}

// round 2
// speedup vs baseline: 1.6934x; 1.6934x over previous
#include <cuda_runtime.h>
#include <math.h>

#define D 128
#define MAXN 50000
#define MAXE 800000

__device__ float g_support[MAXN * D];
__device__ int   g_cnt[MAXN];
__device__ int   g_offs[MAXN];
__device__ int   g_cursor[MAXN];
__device__ int   g_bsums[64];
__device__ int   g_ecol[MAXE];
__device__ float g_eval[MAXE];

// fma.rn.f32x2: packed dual fp32 FMA (sm_100+), acc += a*b elementwise on pairs
#define FMA2(acc, a, b) \
    asm("fma.rn.f32x2 %0, %1, %2, %0;" : "+l"(acc) : "l"(a), "l"(b))

__device__ __forceinline__ unsigned long long pack_dup(float f) {
    unsigned long long r;
    asm("mov.b64 %0, {%1, %1};" : "=l"(r) : "f"(f));
    return r;
}
__device__ __forceinline__ float lo_f(unsigned long long v) {
    return __uint_as_float((unsigned)(v & 0xffffffffull));
}
__device__ __forceinline__ float hi_f(unsigned long long v) {
    return __uint_as_float((unsigned)(v >> 32));
}

// ---------------- CSR build ----------------

__global__ void zero_cnt_kernel(int n) {
    int i = blockIdx.x * blockDim.x + threadIdx.x;
    if (i < n) g_cnt[i] = 0;
}

__global__ void hist_kernel(const int* __restrict__ row, int E) {
    int e = blockIdx.x * blockDim.x + threadIdx.x;
    if (e < E) atomicAdd(&g_cnt[row[e]], 1);
}

__global__ void scan1_kernel(int n) {
    __shared__ int s[1024];
    int i = blockIdx.x * 1024 + threadIdx.x;
    int v = (i < n) ? g_cnt[i] : 0;
    s[threadIdx.x] = v;
    __syncthreads();
    for (int d = 1; d < 1024; d <<= 1) {
        int t = (threadIdx.x >= d) ? s[threadIdx.x - d] : 0;
        __syncthreads();
        s[threadIdx.x] += t;
        __syncthreads();
    }
    if (i < n) g_offs[i] = s[threadIdx.x] - v;  // exclusive within block
    if (threadIdx.x == 1023) g_bsums[blockIdx.x] = s[1023];
}

__global__ void scan2_kernel(int nb) {
    if (threadIdx.x == 0) {
        int run = 0;
        for (int j = 0; j < nb; j++) { int t = g_bsums[j]; g_bsums[j] = run; run += t; }
    }
}

__global__ void scan3_kernel(int n) {
    int i = blockIdx.x * blockDim.x + threadIdx.x;
    if (i < n) {
        int o = g_offs[i] + g_bsums[i >> 10];
        g_offs[i] = o;
        g_cursor[i] = o;
    }
}

__global__ void scatter_kernel(const int* __restrict__ row, const int* __restrict__ col,
                               const float* __restrict__ vals, int E) {
    int e = blockIdx.x * blockDim.x + threadIdx.x;
    if (e < E) {
        int pos = atomicAdd(&g_cursor[row[e]], 1);
        g_ecol[pos] = col[e];
        g_eval[pos] = vals[e];
    }
}

// ---------------- gather SpMM: support = (1-alpha)*A*input + alpha*h0 ----------------

__global__ void gather_kernel(const float* __restrict__ input,
                              const float* __restrict__ h0,
                              const float* __restrict__ alpha_p, int N) {
    int wid  = (blockIdx.x * blockDim.x + threadIdx.x) >> 5;
    int lane = threadIdx.x & 31;
    if (wid >= N) return;
    int beg = g_offs[wid];
    int end = beg + g_cnt[wid];
    const float4* in4 = (const float4*)input;

    float ax = 0.f, ay = 0.f, az = 0.f, aw = 0.f;
    int j = beg;
    for (; j + 4 <= end; j += 4) {
        int   c0 = g_ecol[j],   c1 = g_ecol[j+1], c2 = g_ecol[j+2], c3 = g_ecol[j+3];
        float v0 = g_eval[j],   v1 = g_eval[j+1], v2 = g_eval[j+2], v3 = g_eval[j+3];
        float4 x0 = in4[(size_t)c0 * 32 + lane];
        float4 x1 = in4[(size_t)c1 * 32 + lane];
        float4 x2 = in4[(size_t)c2 * 32 + lane];
        float4 x3 = in4[(size_t)c3 * 32 + lane];
        ax = fmaf(v0, x0.x, fmaf(v1, x1.x, fmaf(v2, x2.x, fmaf(v3, x3.x, ax))));
        ay = fmaf(v0, x0.y, fmaf(v1, x1.y, fmaf(v2, x2.y, fmaf(v3, x3.y, ay))));
        az = fmaf(v0, x0.z, fmaf(v1, x1.z, fmaf(v2, x2.z, fmaf(v3, x3.z, az))));
        aw = fmaf(v0, x0.w, fmaf(v1, x1.w, fmaf(v2, x2.w, fmaf(v3, x3.w, aw))));
    }
    for (; j < end; j++) {
        int c = g_ecol[j];
        float v = g_eval[j];
        float4 x = in4[(size_t)c * 32 + lane];
        ax = fmaf(v, x.x, ax);
        ay = fmaf(v, x.y, ay);
        az = fmaf(v, x.z, az);
        aw = fmaf(v, x.w, aw);
    }

    float a = *alpha_p, oma = 1.f - a;
    float4 h = ((const float4*)h0)[(size_t)wid * 32 + lane];
    float4 o = make_float4(fmaf(oma, ax, a * h.x),
                           fmaf(oma, ay, a * h.y),
                           fmaf(oma, az, a * h.z),
                           fmaf(oma, aw, a * h.w));
    ((float4*)g_support)[(size_t)wid * 32 + lane] = o;
}

// ---------------- GEMM: out = theta*(support@W) + (1-theta)*support ----------------
// Block = 128 threads (4 warps), 32 rows per block, 8 rows per warp.
// support staged in smem as duplicated f32x2 pairs; inner loop pure fma.rn.f32x2.

#define GEMM_ROWS 32

__global__ void __launch_bounds__(128) gemm_kernel(
        const float* __restrict__ W,
        const float* __restrict__ lamda_p,
        const int* __restrict__ l_p,
        float* __restrict__ out, int N) {
    __shared__ unsigned long long sp[GEMM_ROWS][D];  // 32 KB: sp[r][k] = (s,s)
    int tid  = threadIdx.x;
    int lane = tid & 31;
    int w    = tid >> 5;
    int rowBase = blockIdx.x * GEMM_ROWS;

    // stage support rows as duplicated pairs: 32 rows x 32 float4 = 1024 items
    for (int t = tid; t < GEMM_ROWS * 32; t += 128) {
        int r = t >> 5;
        int q = t & 31;
        int gr = rowBase + r;
        float4 s4 = (gr < N) ? ((const float4*)g_support)[(size_t)gr * 32 + q]
                             : make_float4(0.f, 0.f, 0.f, 0.f);
        sp[r][q * 4 + 0] = pack_dup(s4.x);
        sp[r][q * 4 + 1] = pack_dup(s4.y);
        sp[r][q * 4 + 2] = pack_dup(s4.z);
        sp[r][q * 4 + 3] = pack_dup(s4.w);
    }
    __syncthreads();

    unsigned long long acc01[8], acc23[8];
#pragma unroll
    for (int r = 0; r < 8; r++) { acc01[r] = 0ull; acc23[r] = 0ull; }

    const ulonglong2* W2 = (const ulonglong2*)W;  // row k: 32 ull2; lane's float4 = W2[k*32+lane]

#pragma unroll 4
    for (int kg = 0; kg < 32; kg++) {
        int k0 = kg * 4;
        ulonglong2 w0 = __ldg(&W2[(size_t)(k0 + 0) * 32 + lane]);
        ulonglong2 w1 = __ldg(&W2[(size_t)(k0 + 1) * 32 + lane]);
        ulonglong2 w2 = __ldg(&W2[(size_t)(k0 + 2) * 32 + lane]);
        ulonglong2 w3 = __ldg(&W2[(size_t)(k0 + 3) * 32 + lane]);
#pragma unroll
        for (int r = 0; r < 8; r++) {
            int rr = w * 8 + r;
            const ulonglong2* srow = (const ulonglong2*)sp[rr];
            ulonglong2 sA = srow[kg * 2 + 0];  // (ss[k0], ss[k0+1])
            ulonglong2 sB = srow[kg * 2 + 1];  // (ss[k0+2], ss[k0+3])
            FMA2(acc01[r], w0.x, sA.x); FMA2(acc23[r], w0.y, sA.x);
            FMA2(acc01[r], w1.x, sA.y); FMA2(acc23[r], w1.y, sA.y);
            FMA2(acc01[r], w2.x, sB.x); FMA2(acc23[r], w2.y, sB.x);
            FMA2(acc01[r], w3.x, sB.y); FMA2(acc23[r], w3.y, sB.y);
        }
    }

    float theta = logf(*lamda_p / (float)(*l_p) + 1.0f);
    float om = 1.0f - theta;

#pragma unroll
    for (int r = 0; r < 8; r++) {
        int rr = w * 8 + r;
        int gr = rowBase + rr;
        if (gr >= N) continue;
        const ulonglong2* srow = (const ulonglong2*)sp[rr];
        ulonglong2 s01 = srow[lane * 2 + 0];
        ulonglong2 s23 = srow[lane * 2 + 1];
        float4 o;
        o.x = fmaf(theta, lo_f(acc01[r]), om * lo_f(s01.x));
        o.y = fmaf(theta, hi_f(acc01[r]), om * lo_f(s01.y));
        o.z = fmaf(theta, lo_f(acc23[r]), om * lo_f(s23.x));
        o.w = fmaf(theta, hi_f(acc23[r]), om * lo_f(s23.y));
        ((float4*)out)[(size_t)gr * 32 + lane] = o;
    }
}

// ---------------- launch ----------------

extern "C" void kernel_launch(void* const* d_in, const int* in_sizes, int n_in,
                              void* d_out, int out_size) {
    const float* input  = (const float*)d_in[0];
    const float* h0     = (const float*)d_in[1];
    const float* vals   = (const float*)d_in[2];
    const float* W      = (const float*)d_in[3];
    const float* lamda  = (const float*)d_in[4];
    const float* alpha  = (const float*)d_in[5];
    const int*   row    = (const int*)d_in[6];
    const int*   col    = (const int*)d_in[7];
    const int*   l      = (const int*)d_in[8];
    float* out = (float*)d_out;

    int N = in_sizes[0] / D;
    int E = in_sizes[2];

    zero_cnt_kernel<<<(N + 255) / 256, 256>>>(N);
    hist_kernel<<<(E + 255) / 256, 256>>>(row, E);
    int nScanBlocks = (N + 1023) / 1024;
    scan1_kernel<<<nScanBlocks, 1024>>>(N);
    scan2_kernel<<<1, 32>>>(nScanBlocks);
    scan3_kernel<<<(N + 255) / 256, 256>>>(N);
    scatter_kernel<<<(E + 255) / 256, 256>>>(row, col, vals, E);

    gather_kernel<<<(N * 32 + 255) / 256, 256>>>(input, h0, alpha, N);

    gemm_kernel<<<(N + GEMM_ROWS - 1) / GEMM_ROWS, 128>>>(W, lamda, l, out, N);
}